// round 7
// baseline (speedup 1.0000x reference)
#include <cuda_runtime.h>
#include <cuda_fp16.h>

#define W_   128
#define H_   256
#define D_   256
#define NVOX 16777216         // 2*256*256*128
#define NTHR 2097152          // NVOX/8
#define SD_  32768            // stride along D = H_*W_
#define LAMB 0.01f
#define FULLM 0xffffffffu

// Persistent scratch: z fields stored in fp16 (32 MB each).
__device__ __half g_z0[NVOX];
__device__ __half g_z1[NVOX];
__device__ __half g_z2[NVOX];

struct F8 { float v[8]; };

__device__ __forceinline__ F8 ld8(const float* p, int idx) {
    float4 a = *(const float4*)(p + idx);
    float4 b = *(const float4*)(p + idx + 4);
    F8 r;
    r.v[0]=a.x; r.v[1]=a.y; r.v[2]=a.z; r.v[3]=a.w;
    r.v[4]=b.x; r.v[5]=b.y; r.v[6]=b.z; r.v[7]=b.w;
    return r;
}
__device__ __forceinline__ void st8(float* p, int idx, const F8& r) {
    *(float4*)(p + idx)     = make_float4(r.v[0], r.v[1], r.v[2], r.v[3]);
    *(float4*)(p + idx + 4) = make_float4(r.v[4], r.v[5], r.v[6], r.v[7]);
}
__device__ __forceinline__ F8 ldh8(const __half* p, int idx) {
    uint4 raw = *(const uint4*)(p + idx);       // 8 halves = 16B
    F8 r;
    float2 f;
    f = __half22float2(*(const __half2*)&raw.x); r.v[0]=f.x; r.v[1]=f.y;
    f = __half22float2(*(const __half2*)&raw.y); r.v[2]=f.x; r.v[3]=f.y;
    f = __half22float2(*(const __half2*)&raw.z); r.v[4]=f.x; r.v[5]=f.y;
    f = __half22float2(*(const __half2*)&raw.w); r.v[6]=f.x; r.v[7]=f.y;
    return r;
}
__device__ __forceinline__ void sth8(__half* p, int idx, const F8& r) {
    uint4 raw;
    __half2 h;
    h = __floats2half2_rn(r.v[0], r.v[1]); raw.x = *(const unsigned int*)&h;
    h = __floats2half2_rn(r.v[2], r.v[3]); raw.y = *(const unsigned int*)&h;
    h = __floats2half2_rn(r.v[4], r.v[5]); raw.z = *(const unsigned int*)&h;
    h = __floats2half2_rn(r.v[6], r.v[7]); raw.w = *(const unsigned int*)&h;
    *(uint4*)(p + idx) = raw;
}

__device__ __forceinline__ float zf(float t, float s) { return t - LAMB * (t - s); }
__device__ __forceinline__ float clip(float x, float sg) { return fminf(fmaxf(x, -sg), sg); }
__device__ __forceinline__ F8 zf8(const F8& t, const F8& s) {
    F8 z;
#pragma unroll
    for (int j = 0; j < 8; j++) z.v[j] = zf(t.v[j], s.v[j]);
    return z;
}
// one dual stage: pn = clip(p - dz, sg); return pn + nt*(pn - p)
__device__ __forceinline__ float dualu(float p, float dz, float sg, float nt) {
    float pn = clip(p - dz, sg);
    return pn + nt * (pn - p);
}

// ---------------- cascade 0 (fp32 inputs, NS=1 chains) ----------------
__global__ __launch_bounds__(256)
void dtv_c0(const float* __restrict__ image, const float* __restrict__ sino,
            const float* __restrict__ sig, const float* __restrict__ ntp,
            __half* __restrict__ wz0, __half* __restrict__ wz1,
            float* __restrict__ tout, float* __restrict__ out0)
{
    int t = blockIdx.x * 256 + threadIdx.x;
    int idx = t << 3;
    int w0 = idx & (W_ - 1);                  // 0,8,...,120
    int h = (idx >> 7) & (H_ - 1);
    int d = (idx >> 15) & (D_ - 1);
    bool dhi = (d < D_ - 1), dlo = (d > 0);
    bool hhi = (h < H_ - 1), hlo = (h > 0);
    bool wlo = (w0 > 0), whi = (w0 == W_ - 8);

    F8 t8 = ld8(image, idx);
    F8 s8 = ld8(sino, idx);
    F8 z  = zf8(t8, s8);

    float sg0 = __ldg(sig+0), sg1 = __ldg(sig+1), sg2 = __ldg(sig+2), sg3 = __ldg(sig+3);
    float nt0 = __ldg(ntp + 0);

    float o[8];
#pragma unroll
    for (int j = 0; j < 8; j++) o[j] = clip(z.v[j], sg3);

    // ---- D axis ----
    {
        F8 zp = dhi ? zf8(ld8(image, idx + SD_), ld8(sino, idx + SD_)) : z;
        F8 zm = dlo ? zf8(ld8(image, idx - SD_), ld8(sino, idx - SD_)) : z;
        float lm = dlo ? 1.f : 0.f;
#pragma unroll
        for (int j = 0; j < 8; j++) {
            float pe  = dualu(0.f, zp.v[j] - z.v[j], sg0, nt0);
            float pem = dualu(0.f, z.v[j] - zm.v[j], sg0, nt0);
            o[j] += lm * pem - pe;
        }
    }
    // ---- H axis ----
    {
        F8 zp = hhi ? zf8(ld8(image, idx + W_), ld8(sino, idx + W_)) : z;
        F8 zm = hlo ? zf8(ld8(image, idx - W_), ld8(sino, idx - W_)) : z;
        float lm = hlo ? 1.f : 0.f;
#pragma unroll
        for (int j = 0; j < 8; j++) {
            float qe  = dualu(0.f, zp.v[j] - z.v[j], sg1, nt0);
            float qem = dualu(0.f, z.v[j] - zm.v[j], sg1, nt0);
            o[j] += lm * qem - qe;
        }
    }
    // ---- W axis ----
    {
        float zn = __shfl_down_sync(FULLM, z.v[0], 1);
        if (whi) zn = z.v[7];                 // boundary: dz = 0
        float s[8];
#pragma unroll
        for (int j = 0; j < 7; j++) s[j] = dualu(0.f, z.v[j+1] - z.v[j], sg2, nt0);
        s[7] = dualu(0.f, zn - z.v[7], sg2, nt0);
        float sem = __shfl_up_sync(FULLM, s[7], 1);
        o[0] += (wlo ? sem : 0.f) - s[0];
#pragma unroll
        for (int j = 1; j < 8; j++) o[j] += s[j-1] - s[j];
    }

    F8 o8; F8 z1;
#pragma unroll
    for (int j = 0; j < 8; j++) { o8.v[j] = o[j]; z1.v[j] = zf(o[j], s8.v[j]); }

    st8(tout, idx, o8);
    st8(out0, idx, t8);
    sth8(wz0, idx, z);
    sth8(wz1, idx, z1);
}

// ---------------- cascades 1 & 2 (fp16 z fields, NS-stage chains) ----------------
template <int NS, bool LAST>
__global__ __launch_bounds__(256)
void dtv_chain(const __half* __restrict__ za, const __half* __restrict__ zb,
               const __half* __restrict__ zc, const float* __restrict__ sino,
               const float* __restrict__ sig, const float* __restrict__ ntp,
               __half* __restrict__ wz, float* __restrict__ tout)
{
    int t = blockIdx.x * 256 + threadIdx.x;
    int idx = t << 3;
    int w0 = idx & (W_ - 1);
    int h = (idx >> 7) & (H_ - 1);
    int d = (idx >> 15) & (D_ - 1);
    bool dhi = (d < D_ - 1), dlo = (d > 0);
    bool hhi = (h < H_ - 1), hlo = (h > 0);
    bool wlo = (w0 > 0), whi = (w0 == W_ - 8);

    const __half* zs[3] = { za, zb, zc };

    float sg0 = __ldg(sig+0), sg1 = __ldg(sig+1), sg2 = __ldg(sig+2), sg3 = __ldg(sig+3);
    float nt[3];
#pragma unroll
    for (int c = 0; c < NS; c++) nt[c] = __ldg(ntp + c);

    F8 z[NS];
#pragma unroll
    for (int c = 0; c < NS; c++) z[c] = ldh8(zs[c], idx);

    float o[8];
#pragma unroll
    for (int j = 0; j < 8; j++) o[j] = clip(z[NS-1].v[j], sg3);

    // ---- D axis ----
    {
        float p[8], pm[8];
#pragma unroll
        for (int j = 0; j < 8; j++) { p[j] = 0.f; pm[j] = 0.f; }
#pragma unroll
        for (int c = 0; c < NS; c++) {
            F8 zp = dhi ? ldh8(zs[c], idx + SD_) : z[c];
            F8 zm = dlo ? ldh8(zs[c], idx - SD_) : z[c];
#pragma unroll
            for (int j = 0; j < 8; j++) {
                p[j]  = dualu(p[j],  zp.v[j] - z[c].v[j], sg0, nt[c]);
                pm[j] = dualu(pm[j], z[c].v[j] - zm.v[j], sg0, nt[c]);
            }
        }
        float lm = dlo ? 1.f : 0.f;
#pragma unroll
        for (int j = 0; j < 8; j++) o[j] += lm * pm[j] - p[j];
    }
    // ---- H axis ----
    {
        float p[8], pm[8];
#pragma unroll
        for (int j = 0; j < 8; j++) { p[j] = 0.f; pm[j] = 0.f; }
#pragma unroll
        for (int c = 0; c < NS; c++) {
            F8 zp = hhi ? ldh8(zs[c], idx + W_) : z[c];
            F8 zm = hlo ? ldh8(zs[c], idx - W_) : z[c];
#pragma unroll
            for (int j = 0; j < 8; j++) {
                p[j]  = dualu(p[j],  zp.v[j] - z[c].v[j], sg1, nt[c]);
                pm[j] = dualu(pm[j], z[c].v[j] - zm.v[j], sg1, nt[c]);
            }
        }
        float lm = hlo ? 1.f : 0.f;
#pragma unroll
        for (int j = 0; j < 8; j++) o[j] += lm * pm[j] - p[j];
    }
    // ---- W axis ----
    {
        float s[8];
#pragma unroll
        for (int j = 0; j < 8; j++) s[j] = 0.f;
#pragma unroll
        for (int c = 0; c < NS; c++) {
            float zn = __shfl_down_sync(FULLM, z[c].v[0], 1);
            if (whi) zn = z[c].v[7];
#pragma unroll
            for (int j = 0; j < 7; j++) s[j] = dualu(s[j], z[c].v[j+1] - z[c].v[j], sg2, nt[c]);
            s[7] = dualu(s[7], zn - z[c].v[7], sg2, nt[c]);
        }
        float sem = __shfl_up_sync(FULLM, s[7], 1);
        o[0] += (wlo ? sem : 0.f) - s[0];
#pragma unroll
        for (int j = 1; j < 8; j++) o[j] += s[j-1] - s[j];
    }

    F8 o8;
#pragma unroll
    for (int j = 0; j < 8; j++) o8.v[j] = o[j];
    st8(tout, idx, o8);

    if (!LAST) {
        F8 s8 = ld8(sino, idx);
        F8 zn;
#pragma unroll
        for (int j = 0; j < 8; j++) zn.v[j] = zf(o[j], s8.v[j]);
        sth8(wz, idx, zn);
    }
}

extern "C" void kernel_launch(void* const* d_in, const int* in_sizes, int n_in,
                              void* d_out, int out_size)
{
    const float* image = nullptr;
    const float* sino  = nullptr;
    const float* sigma = nullptr;
    const float* ntv   = nullptr;
    for (int i = 0; i < n_in; i++) {
        if (in_sizes[i] == 4) sigma = (const float*)d_in[i];
        else if (in_sizes[i] == 3) ntv = (const float*)d_in[i];
        else if (!image) image = (const float*)d_in[i];
        else if (!sino)  sino  = (const float*)d_in[i];
    }
    float* out = (float*)d_out;

    __half *z0a, *z1a, *z2a;
    cudaGetSymbolAddress((void**)&z0a, g_z0);
    cudaGetSymbolAddress((void**)&z1a, g_z1);
    cudaGetSymbolAddress((void**)&z2a, g_z2);

    dim3 grid(NTHR / 256), block(256);

    // cascade 0: writes out0, t1, z0, z1
    dtv_c0<<<grid, block>>>(image, sino, sigma, ntv,
                            z0a, z1a, out + 1u * NVOX, out);
    // cascade 1: reads z0,z1; writes t2, z2
    dtv_chain<2, false><<<grid, block>>>(z0a, z1a, nullptr, sino, sigma, ntv,
                                         z2a, out + 2u * NVOX);
    // cascade 2: reads z0,z1,z2; writes t3
    dtv_chain<3, true ><<<grid, block>>>(z0a, z1a, z2a, nullptr, sigma, ntv,
                                         nullptr, out + 3u * NVOX);
}

// round 8
// speedup vs baseline: 1.1364x; 1.1364x over previous
#include <cuda_runtime.h>
#include <cuda_fp16.h>

#define W_   128
#define H_   256
#define D_   256
#define NVOX 16777216         // 2*256*256*128
#define NVEC 4194304          // NVOX/4
#define SD_  32768            // stride along D = H_*W_
#define LAMB 0.01f
#define FULLM 0xffffffffu

// Scratch: {z0,z1} packed as half2 per voxel (64 MB) + z2 fp16 (32 MB).
__device__ unsigned int g_zpk[NVOX];
__device__ __half       g_z2[NVOX];

struct ZP { float a[4]; float b[4]; };   // a = z0 lanes, b = z1 lanes

__device__ __forceinline__ float4 ld4(const float* p, int idx) { return *(const float4*)(p + idx); }

__device__ __forceinline__ ZP unpk(uint4 raw) {
    ZP r; float2 f;
    f = __half22float2(*(const __half2*)&raw.x); r.a[0]=f.x; r.b[0]=f.y;
    f = __half22float2(*(const __half2*)&raw.y); r.a[1]=f.x; r.b[1]=f.y;
    f = __half22float2(*(const __half2*)&raw.z); r.a[2]=f.x; r.b[2]=f.y;
    f = __half22float2(*(const __half2*)&raw.w); r.a[3]=f.x; r.b[3]=f.y;
    return r;
}
__device__ __forceinline__ ZP ldpk(const unsigned int* p, int idx) {
    return unpk(*(const uint4*)(p + idx));
}
__device__ __forceinline__ void stpk(unsigned int* p, int idx,
                                     const float* a, const float* b) {
    uint4 raw;
    __half2 h;
    h = __floats2half2_rn(a[0], b[0]); raw.x = *(const unsigned int*)&h;
    h = __floats2half2_rn(a[1], b[1]); raw.y = *(const unsigned int*)&h;
    h = __floats2half2_rn(a[2], b[2]); raw.z = *(const unsigned int*)&h;
    h = __floats2half2_rn(a[3], b[3]); raw.w = *(const unsigned int*)&h;
    *(uint4*)(p + idx) = raw;
}
// fp16 scalar-array vec4 load/store (8B)
__device__ __forceinline__ void ldh4(const __half* p, int idx, float* v) {
    uint2 raw = *(const uint2*)(p + idx);
    float2 f;
    f = __half22float2(*(const __half2*)&raw.x); v[0]=f.x; v[1]=f.y;
    f = __half22float2(*(const __half2*)&raw.y); v[2]=f.x; v[3]=f.y;
}
__device__ __forceinline__ void sth4(__half* p, int idx, const float* v) {
    uint2 raw;
    __half2 h;
    h = __floats2half2_rn(v[0], v[1]); raw.x = *(const unsigned int*)&h;
    h = __floats2half2_rn(v[2], v[3]); raw.y = *(const unsigned int*)&h;
    *(uint2*)(p + idx) = raw;
}

__device__ __forceinline__ float zf(float t, float s) { return t - LAMB * (t - s); }
__device__ __forceinline__ float clip(float x, float sg) { return fminf(fmaxf(x, -sg), sg); }
// one dual stage
__device__ __forceinline__ float dualu(float p, float dz, float sg, float nt) {
    float pn = clip(p - dz, sg);
    return pn + nt * (pn - p);
}
__device__ __forceinline__ float chain2(float dz0, float dz1, float sg, float nt0, float nt1) {
    return dualu(dualu(0.f, dz0, sg, nt0), dz1, sg, nt1);
}
__device__ __forceinline__ float chain3(float dz0, float dz1, float dz2,
                                        float sg, float nt0, float nt1, float nt2) {
    return dualu(dualu(dualu(0.f, dz0, sg, nt0), dz1, sg, nt1), dz2, sg, nt2);
}

// ---------------- cascade 0 ----------------
// reads image,sino stencils; writes out0, t1, packed {z0,z1}.
__global__ __launch_bounds__(256)
void dtv_c0(const float* __restrict__ image, const float* __restrict__ sino,
            const float* __restrict__ sig, const float* __restrict__ ntp,
            unsigned int* __restrict__ wzpk,
            float* __restrict__ tout, float* __restrict__ out0)
{
    int v = blockIdx.x * 256 + threadIdx.x;
    int idx = v << 2;
    int lane = threadIdx.x & 31;       // warp == one W row; lane L covers w=4L..4L+3
    int h = (idx >> 7) & (H_ - 1);
    int d = (idx >> 15) & (D_ - 1);
    bool dhi = (d < D_ - 1), dlo = (d > 0);
    bool hhi = (h < H_ - 1), hlo = (h > 0);

    float4 t4 = ld4(image, idx);
    float4 s4 = ld4(sino, idx);
    float z[4] = { zf(t4.x, s4.x), zf(t4.y, s4.y), zf(t4.z, s4.z), zf(t4.w, s4.w) };

    float sg0 = __ldg(sig+0), sg1 = __ldg(sig+1), sg2 = __ldg(sig+2), sg3 = __ldg(sig+3);
    float nt0 = __ldg(ntp + 0);

    float o[4];
#pragma unroll
    for (int j = 0; j < 4; j++) o[j] = clip(z[j], sg3);

    // ---- D axis ----
    {
        float zp[4], zm[4];
        if (dhi) { float4 a = ld4(image, idx + SD_), b = ld4(sino, idx + SD_);
                   zp[0]=zf(a.x,b.x); zp[1]=zf(a.y,b.y); zp[2]=zf(a.z,b.z); zp[3]=zf(a.w,b.w); }
        else     { zp[0]=z[0]; zp[1]=z[1]; zp[2]=z[2]; zp[3]=z[3]; }
        if (dlo) { float4 a = ld4(image, idx - SD_), b = ld4(sino, idx - SD_);
                   zm[0]=zf(a.x,b.x); zm[1]=zf(a.y,b.y); zm[2]=zf(a.z,b.z); zm[3]=zf(a.w,b.w); }
        else     { zm[0]=z[0]; zm[1]=z[1]; zm[2]=z[2]; zm[3]=z[3]; }
        float lm = dlo ? 1.f : 0.f;
#pragma unroll
        for (int j = 0; j < 4; j++) {
            float pe  = dualu(0.f, zp[j] - z[j], sg0, nt0);
            float pem = dualu(0.f, z[j] - zm[j], sg0, nt0);
            o[j] += lm * pem - pe;
        }
    }
    // ---- H axis ----
    {
        float zp[4], zm[4];
        if (hhi) { float4 a = ld4(image, idx + W_), b = ld4(sino, idx + W_);
                   zp[0]=zf(a.x,b.x); zp[1]=zf(a.y,b.y); zp[2]=zf(a.z,b.z); zp[3]=zf(a.w,b.w); }
        else     { zp[0]=z[0]; zp[1]=z[1]; zp[2]=z[2]; zp[3]=z[3]; }
        if (hlo) { float4 a = ld4(image, idx - W_), b = ld4(sino, idx - W_);
                   zm[0]=zf(a.x,b.x); zm[1]=zf(a.y,b.y); zm[2]=zf(a.z,b.z); zm[3]=zf(a.w,b.w); }
        else     { zm[0]=z[0]; zm[1]=z[1]; zm[2]=z[2]; zm[3]=z[3]; }
        float lm = hlo ? 1.f : 0.f;
#pragma unroll
        for (int j = 0; j < 4; j++) {
            float qe  = dualu(0.f, zp[j] - z[j], sg1, nt0);
            float qem = dualu(0.f, z[j] - zm[j], sg1, nt0);
            o[j] += lm * qem - qe;
        }
    }
    // ---- W axis ----
    {
        float zn = __shfl_down_sync(FULLM, z[0], 1);
        if (lane == 31) zn = z[3];
        float s[4];
        s[0] = dualu(0.f, z[1] - z[0], sg2, nt0);
        s[1] = dualu(0.f, z[2] - z[1], sg2, nt0);
        s[2] = dualu(0.f, z[3] - z[2], sg2, nt0);
        s[3] = dualu(0.f, zn   - z[3], sg2, nt0);
        float sem = __shfl_up_sync(FULLM, s[3], 1);
        o[0] += ((lane > 0) ? sem : 0.f) - s[0];
        o[1] += s[0] - s[1];
        o[2] += s[1] - s[2];
        o[3] += s[2] - s[3];
    }

    *(float4*)(tout + idx) = make_float4(o[0], o[1], o[2], o[3]);
    *(float4*)(out0 + idx) = t4;
    float z1v[4] = { zf(o[0], s4.x), zf(o[1], s4.y), zf(o[2], s4.z), zf(o[3], s4.w) };
    stpk(wzpk, idx, z, z1v);
}

// ---------------- cascade 1 ----------------
// reads packed {z0,z1} at 5 stencil points + sino; writes t2 and z2 (fp16).
__global__ __launch_bounds__(256)
void dtv_c1(const unsigned int* __restrict__ zpk, const float* __restrict__ sino,
            const float* __restrict__ sig, const float* __restrict__ ntp,
            __half* __restrict__ wz2, float* __restrict__ tout)
{
    int v = blockIdx.x * 256 + threadIdx.x;
    int idx = v << 2;
    int lane = threadIdx.x & 31;
    int h = (idx >> 7) & (H_ - 1);
    int d = (idx >> 15) & (D_ - 1);
    bool dhi = (d < D_ - 1), dlo = (d > 0);
    bool hhi = (h < H_ - 1), hlo = (h > 0);

    float sg0 = __ldg(sig+0), sg1 = __ldg(sig+1), sg2 = __ldg(sig+2), sg3 = __ldg(sig+3);
    float nt0 = __ldg(ntp + 0), nt1 = __ldg(ntp + 1);

    uint4 rawx = *(const uint4*)(zpk + idx);
    ZP zx = unpk(rawx);

    float o[4];
#pragma unroll
    for (int j = 0; j < 4; j++) o[j] = clip(zx.b[j], sg3);

    // ---- D axis ----
    {
        ZP zp = dhi ? ldpk(zpk, idx + SD_) : zx;
        ZP zm = dlo ? ldpk(zpk, idx - SD_) : zx;
        float lm = dlo ? 1.f : 0.f;
#pragma unroll
        for (int j = 0; j < 4; j++) {
            float pe  = chain2(zp.a[j] - zx.a[j], zp.b[j] - zx.b[j], sg0, nt0, nt1);
            float pem = chain2(zx.a[j] - zm.a[j], zx.b[j] - zm.b[j], sg0, nt0, nt1);
            o[j] += lm * pem - pe;
        }
    }
    // ---- H axis ----
    {
        ZP zp = hhi ? ldpk(zpk, idx + W_) : zx;
        ZP zm = hlo ? ldpk(zpk, idx - W_) : zx;
        float lm = hlo ? 1.f : 0.f;
#pragma unroll
        for (int j = 0; j < 4; j++) {
            float qe  = chain2(zp.a[j] - zx.a[j], zp.b[j] - zx.b[j], sg1, nt0, nt1);
            float qem = chain2(zx.a[j] - zm.a[j], zx.b[j] - zm.b[j], sg1, nt0, nt1);
            o[j] += lm * qem - qe;
        }
    }
    // ---- W axis ----
    {
        unsigned int nraw = __shfl_down_sync(FULLM, rawx.x, 1);
        float2 nf = __half22float2(*(const __half2*)&nraw);
        float za4 = (lane == 31) ? zx.a[3] : nf.x;
        float zb4 = (lane == 31) ? zx.b[3] : nf.y;
        float s[4];
        s[0] = chain2(zx.a[1] - zx.a[0], zx.b[1] - zx.b[0], sg2, nt0, nt1);
        s[1] = chain2(zx.a[2] - zx.a[1], zx.b[2] - zx.b[1], sg2, nt0, nt1);
        s[2] = chain2(zx.a[3] - zx.a[2], zx.b[3] - zx.b[2], sg2, nt0, nt1);
        s[3] = chain2(za4     - zx.a[3], zb4     - zx.b[3], sg2, nt0, nt1);
        float sem = __shfl_up_sync(FULLM, s[3], 1);
        o[0] += ((lane > 0) ? sem : 0.f) - s[0];
        o[1] += s[0] - s[1];
        o[2] += s[1] - s[2];
        o[3] += s[2] - s[3];
    }

    *(float4*)(tout + idx) = make_float4(o[0], o[1], o[2], o[3]);
    float4 s4 = ld4(sino, idx);
    float z2v[4] = { zf(o[0], s4.x), zf(o[1], s4.y), zf(o[2], s4.z), zf(o[3], s4.w) };
    sth4(wz2, idx, z2v);
}

// ---------------- cascade 2 ----------------
// reads packed {z0,z1} + z2 at 5 stencil points; writes t3.
__global__ __launch_bounds__(256)
void dtv_c2(const unsigned int* __restrict__ zpk, const __half* __restrict__ z2,
            const float* __restrict__ sig, const float* __restrict__ ntp,
            float* __restrict__ tout)
{
    int v = blockIdx.x * 256 + threadIdx.x;
    int idx = v << 2;
    int lane = threadIdx.x & 31;
    int h = (idx >> 7) & (H_ - 1);
    int d = (idx >> 15) & (D_ - 1);
    bool dhi = (d < D_ - 1), dlo = (d > 0);
    bool hhi = (h < H_ - 1), hlo = (h > 0);

    float sg0 = __ldg(sig+0), sg1 = __ldg(sig+1), sg2 = __ldg(sig+2), sg3 = __ldg(sig+3);
    float nt0 = __ldg(ntp + 0), nt1 = __ldg(ntp + 1), nt2 = __ldg(ntp + 2);

    uint4 rawx = *(const uint4*)(zpk + idx);
    ZP zx = unpk(rawx);
    float zcx[4];
    ldh4(z2, idx, zcx);

    float o[4];
#pragma unroll
    for (int j = 0; j < 4; j++) o[j] = clip(zcx[j], sg3);

    // ---- D axis ----
    {
        ZP zp = dhi ? ldpk(zpk, idx + SD_) : zx;
        ZP zm = dlo ? ldpk(zpk, idx - SD_) : zx;
        float cp[4], cm[4];
        if (dhi) ldh4(z2, idx + SD_, cp); else { cp[0]=zcx[0]; cp[1]=zcx[1]; cp[2]=zcx[2]; cp[3]=zcx[3]; }
        if (dlo) ldh4(z2, idx - SD_, cm); else { cm[0]=zcx[0]; cm[1]=zcx[1]; cm[2]=zcx[2]; cm[3]=zcx[3]; }
        float lm = dlo ? 1.f : 0.f;
#pragma unroll
        for (int j = 0; j < 4; j++) {
            float pe  = chain3(zp.a[j]-zx.a[j], zp.b[j]-zx.b[j], cp[j]-zcx[j], sg0, nt0, nt1, nt2);
            float pem = chain3(zx.a[j]-zm.a[j], zx.b[j]-zm.b[j], zcx[j]-cm[j], sg0, nt0, nt1, nt2);
            o[j] += lm * pem - pe;
        }
    }
    // ---- H axis ----
    {
        ZP zp = hhi ? ldpk(zpk, idx + W_) : zx;
        ZP zm = hlo ? ldpk(zpk, idx - W_) : zx;
        float cp[4], cm[4];
        if (hhi) ldh4(z2, idx + W_, cp); else { cp[0]=zcx[0]; cp[1]=zcx[1]; cp[2]=zcx[2]; cp[3]=zcx[3]; }
        if (hlo) ldh4(z2, idx - W_, cm); else { cm[0]=zcx[0]; cm[1]=zcx[1]; cm[2]=zcx[2]; cm[3]=zcx[3]; }
        float lm = hlo ? 1.f : 0.f;
#pragma unroll
        for (int j = 0; j < 4; j++) {
            float qe  = chain3(zp.a[j]-zx.a[j], zp.b[j]-zx.b[j], cp[j]-zcx[j], sg1, nt0, nt1, nt2);
            float qem = chain3(zx.a[j]-zm.a[j], zx.b[j]-zm.b[j], zcx[j]-cm[j], sg1, nt0, nt1, nt2);
            o[j] += lm * qem - qe;
        }
    }
    // ---- W axis ----
    {
        unsigned int nraw = __shfl_down_sync(FULLM, rawx.x, 1);
        float2 nf = __half22float2(*(const __half2*)&nraw);
        float cnx = __shfl_down_sync(FULLM, zcx[0], 1);
        float za4 = (lane == 31) ? zx.a[3] : nf.x;
        float zb4 = (lane == 31) ? zx.b[3] : nf.y;
        float zc4 = (lane == 31) ? zcx[3]  : cnx;
        float s[4];
        s[0] = chain3(zx.a[1]-zx.a[0], zx.b[1]-zx.b[0], zcx[1]-zcx[0], sg2, nt0, nt1, nt2);
        s[1] = chain3(zx.a[2]-zx.a[1], zx.b[2]-zx.b[1], zcx[2]-zcx[1], sg2, nt0, nt1, nt2);
        s[2] = chain3(zx.a[3]-zx.a[2], zx.b[3]-zx.b[2], zcx[3]-zcx[2], sg2, nt0, nt1, nt2);
        s[3] = chain3(za4-zx.a[3],     zb4-zx.b[3],     zc4-zcx[3],    sg2, nt0, nt1, nt2);
        float sem = __shfl_up_sync(FULLM, s[3], 1);
        o[0] += ((lane > 0) ? sem : 0.f) - s[0];
        o[1] += s[0] - s[1];
        o[2] += s[1] - s[2];
        o[3] += s[2] - s[3];
    }

    *(float4*)(tout + idx) = make_float4(o[0], o[1], o[2], o[3]);
}

extern "C" void kernel_launch(void* const* d_in, const int* in_sizes, int n_in,
                              void* d_out, int out_size)
{
    const float* image = nullptr;
    const float* sino  = nullptr;
    const float* sigma = nullptr;
    const float* ntv   = nullptr;
    for (int i = 0; i < n_in; i++) {
        if (in_sizes[i] == 4) sigma = (const float*)d_in[i];
        else if (in_sizes[i] == 3) ntv = (const float*)d_in[i];
        else if (!image) image = (const float*)d_in[i];
        else if (!sino)  sino  = (const float*)d_in[i];
    }
    float* out = (float*)d_out;

    unsigned int* zpk;
    __half* z2a;
    cudaGetSymbolAddress((void**)&zpk, g_zpk);
    cudaGetSymbolAddress((void**)&z2a, g_z2);

    dim3 grid(NVEC / 256), block(256);

    dtv_c0<<<grid, block>>>(image, sino, sigma, ntv, zpk, out + 1u * NVOX, out);
    dtv_c1<<<grid, block>>>(zpk, sino, sigma, ntv, z2a, out + 2u * NVOX);
    dtv_c2<<<grid, block>>>(zpk, z2a, sigma, ntv, out + 3u * NVOX);
}

// round 10
// speedup vs baseline: 1.2666x; 1.1145x over previous
#include <cuda_runtime.h>
#include <cuda_fp16.h>

#define W_   128
#define H_   256
#define D_   256
#define NVOX 16777216         // 2*256*256*128
#define SD_  32768            // stride along D = H_*W_
#define CH   8                // d-slices per thread
#define LAMB 0.01f
#define FULLM 0xffffffffu

// Scratch: {z0,z1} packed as half2 per voxel (64 MB) + z2 fp16 (32 MB).
__device__ unsigned int g_zpk[NVOX];
__device__ __half       g_z2[NVOX];

struct ZP { float a[4]; float b[4]; };   // a = z0 lanes, b = z1 lanes

__device__ __forceinline__ float4 ld4(const float* p, int idx) { return *(const float4*)(p + idx); }

__device__ __forceinline__ ZP unpk(uint4 raw) {
    ZP r; float2 f;
    f = __half22float2(*(const __half2*)&raw.x); r.a[0]=f.x; r.b[0]=f.y;
    f = __half22float2(*(const __half2*)&raw.y); r.a[1]=f.x; r.b[1]=f.y;
    f = __half22float2(*(const __half2*)&raw.z); r.a[2]=f.x; r.b[2]=f.y;
    f = __half22float2(*(const __half2*)&raw.w); r.a[3]=f.x; r.b[3]=f.y;
    return r;
}
__device__ __forceinline__ ZP ldpk(const unsigned int* p, int idx) {
    return unpk(*(const uint4*)(p + idx));
}
__device__ __forceinline__ void stpk(unsigned int* p, int idx,
                                     const float* a, const float* b) {
    uint4 raw;
    __half2 h;
    h = __floats2half2_rn(a[0], b[0]); raw.x = *(const unsigned int*)&h;
    h = __floats2half2_rn(a[1], b[1]); raw.y = *(const unsigned int*)&h;
    h = __floats2half2_rn(a[2], b[2]); raw.z = *(const unsigned int*)&h;
    h = __floats2half2_rn(a[3], b[3]); raw.w = *(const unsigned int*)&h;
    *(uint4*)(p + idx) = raw;
}
__device__ __forceinline__ void ldh4(const __half* p, int idx, float* v) {
    uint2 raw = *(const uint2*)(p + idx);
    float2 f;
    f = __half22float2(*(const __half2*)&raw.x); v[0]=f.x; v[1]=f.y;
    f = __half22float2(*(const __half2*)&raw.y); v[2]=f.x; v[3]=f.y;
}
__device__ __forceinline__ void sth4(__half* p, int idx, const float* v) {
    uint2 raw;
    __half2 h;
    h = __floats2half2_rn(v[0], v[1]); raw.x = *(const unsigned int*)&h;
    h = __floats2half2_rn(v[2], v[3]); raw.y = *(const unsigned int*)&h;
    *(uint2*)(p + idx) = raw;
}

__device__ __forceinline__ float zf(float t, float s) { return t - LAMB * (t - s); }
__device__ __forceinline__ float clip(float x, float sg) { return fminf(fmaxf(x, -sg), sg); }
__device__ __forceinline__ float dualu(float p, float dz, float sg, float nt) {
    float pn = clip(p - dz, sg);
    return pn + nt * (pn - p);
}
__device__ __forceinline__ float chain2(float dz0, float dz1, float sg, float nt0, float nt1) {
    return dualu(dualu(0.f, dz0, sg, nt0), dz1, sg, nt1);
}
__device__ __forceinline__ float chain3(float dz0, float dz1, float dz2,
                                        float sg, float nt0, float nt1, float nt2) {
    return dualu(dualu(dualu(0.f, dz0, sg, nt0), dz1, sg, nt1), dz2, sg, nt2);
}

// Decode warp -> (b, d0, h); lane covers w = 4*lane .. 4*lane+3
__device__ __forceinline__ int base_idx(int& h, int& d0) {
    int warp = (blockIdx.x * blockDim.x + threadIdx.x) >> 5;
    int lane = threadIdx.x & 31;
    h = warp & (H_ - 1);
    int dchunk = (warp >> 8) & 31;
    int b = warp >> 13;
    d0 = dchunk * CH;
    return ((b * D_ + d0) * H_ + h) * W_ + (lane << 2);
}

// ---------------- cascade 0 ----------------
__global__ __launch_bounds__(256)
void dtv_c0(const float* __restrict__ image, const float* __restrict__ sino,
            const float* __restrict__ sig, const float* __restrict__ ntp,
            unsigned int* __restrict__ wzpk,
            float* __restrict__ tout, float* __restrict__ out0)
{
    int h, d0;
    int idx0 = base_idx(h, d0);
    int lane = threadIdx.x & 31;
    bool hhi = (h < H_ - 1), hlo = (h > 0);

    float sg0 = __ldg(sig+0), sg1 = __ldg(sig+1), sg2 = __ldg(sig+2), sg3 = __ldg(sig+3);
    float nt0 = __ldg(ntp + 0);

    // current center: t,s,z
    float4 tc = ld4(image, idx0);
    float4 sc = ld4(sino, idx0);
    float zc[4] = { zf(tc.x, sc.x), zf(tc.y, sc.y), zf(tc.z, sc.z), zf(tc.w, sc.w) };

    // backward D dual (carry): from z(d0-1); zero if d0 == 0
    float pem[4] = {0.f, 0.f, 0.f, 0.f};
    if (d0 > 0) {
        float4 a = ld4(image, idx0 - SD_), bb = ld4(sino, idx0 - SD_);
        float zm[4] = { zf(a.x,bb.x), zf(a.y,bb.y), zf(a.z,bb.z), zf(a.w,bb.w) };
#pragma unroll
        for (int j = 0; j < 4; j++) pem[j] = dualu(0.f, zc[j] - zm[j], sg0, nt0);
    }

#pragma unroll 2
    for (int dd = 0; dd < CH; dd++) {
        int idx = idx0 + dd * SD_;
        int d = d0 + dd;

        // next-d z (boundary: := center => dz = 0 => dual = 0)
        float4 tn = tc, sn = sc;
        float zn[4];
        if (d < D_ - 1) { tn = ld4(image, idx + SD_); sn = ld4(sino, idx + SD_); }
        zn[0] = zf(tn.x, sn.x); zn[1] = zf(tn.y, sn.y);
        zn[2] = zf(tn.z, sn.z); zn[3] = zf(tn.w, sn.w);
        if (d == D_ - 1) { zn[0]=zc[0]; zn[1]=zc[1]; zn[2]=zc[2]; zn[3]=zc[3]; }

        // H halos at current d
        float zhp[4], zhm[4];
        if (hhi) { float4 a = ld4(image, idx + W_), bb = ld4(sino, idx + W_);
                   zhp[0]=zf(a.x,bb.x); zhp[1]=zf(a.y,bb.y); zhp[2]=zf(a.z,bb.z); zhp[3]=zf(a.w,bb.w); }
        else     { zhp[0]=zc[0]; zhp[1]=zc[1]; zhp[2]=zc[2]; zhp[3]=zc[3]; }
        if (hlo) { float4 a = ld4(image, idx - W_), bb = ld4(sino, idx - W_);
                   zhm[0]=zf(a.x,bb.x); zhm[1]=zf(a.y,bb.y); zhm[2]=zf(a.z,bb.z); zhm[3]=zf(a.w,bb.w); }
        else     { zhm[0]=zc[0]; zhm[1]=zc[1]; zhm[2]=zc[2]; zhm[3]=zc[3]; }

        float o[4], pe[4];
#pragma unroll
        for (int j = 0; j < 4; j++) {
            pe[j] = dualu(0.f, zn[j] - zc[j], sg0, nt0);
            float qe  = dualu(0.f, zhp[j] - zc[j], sg1, nt0);
            float qem = dualu(0.f, zc[j] - zhm[j], sg1, nt0);
            o[j] = clip(zc[j], sg3) + pem[j] - pe[j] + qem - qe;
        }
        // W axis
        {
            float znx = __shfl_down_sync(FULLM, zc[0], 1);
            if (lane == 31) znx = zc[3];
            float s[4];
            s[0] = dualu(0.f, zc[1] - zc[0], sg2, nt0);
            s[1] = dualu(0.f, zc[2] - zc[1], sg2, nt0);
            s[2] = dualu(0.f, zc[3] - zc[2], sg2, nt0);
            s[3] = dualu(0.f, znx   - zc[3], sg2, nt0);
            float sem = __shfl_up_sync(FULLM, s[3], 1);
            o[0] += ((lane > 0) ? sem : 0.f) - s[0];
            o[1] += s[0] - s[1];
            o[2] += s[1] - s[2];
            o[3] += s[2] - s[3];
        }

        *(float4*)(tout + idx) = make_float4(o[0], o[1], o[2], o[3]);
        *(float4*)(out0 + idx) = tc;
        float z1v[4] = { zf(o[0], sc.x), zf(o[1], sc.y), zf(o[2], sc.z), zf(o[3], sc.w) };
        stpk(wzpk, idx, zc, z1v);

        // carry
#pragma unroll
        for (int j = 0; j < 4; j++) { pem[j] = pe[j]; zc[j] = zn[j]; }
        tc = tn; sc = sn;
    }
}

// ---------------- cascade 1 ----------------
__global__ __launch_bounds__(256)
void dtv_c1(const unsigned int* __restrict__ zpk, const float* __restrict__ sino,
            const float* __restrict__ sig, const float* __restrict__ ntp,
            __half* __restrict__ wz2, float* __restrict__ tout)
{
    int h, d0;
    int idx0 = base_idx(h, d0);
    int lane = threadIdx.x & 31;
    bool hhi = (h < H_ - 1), hlo = (h > 0);

    float sg0 = __ldg(sig+0), sg1 = __ldg(sig+1), sg2 = __ldg(sig+2), sg3 = __ldg(sig+3);
    float nt0 = __ldg(ntp + 0), nt1 = __ldg(ntp + 1);

    ZP zc = ldpk(zpk, idx0);
    float pem[4] = {0.f, 0.f, 0.f, 0.f};
    if (d0 > 0) {
        ZP zm = ldpk(zpk, idx0 - SD_);
#pragma unroll
        for (int j = 0; j < 4; j++)
            pem[j] = chain2(zc.a[j] - zm.a[j], zc.b[j] - zm.b[j], sg0, nt0, nt1);
    }

#pragma unroll 2
    for (int dd = 0; dd < CH; dd++) {
        int idx = idx0 + dd * SD_;
        int d = d0 + dd;

        ZP zn = (d < D_ - 1) ? ldpk(zpk, idx + SD_) : zc;
        ZP zhp = hhi ? ldpk(zpk, idx + W_) : zc;
        ZP zhm = hlo ? ldpk(zpk, idx - W_) : zc;

        float o[4], pe[4];
#pragma unroll
        for (int j = 0; j < 4; j++) {
            pe[j] = chain2(zn.a[j] - zc.a[j],  zn.b[j] - zc.b[j],  sg0, nt0, nt1);
            float qe  = chain2(zhp.a[j] - zc.a[j], zhp.b[j] - zc.b[j], sg1, nt0, nt1);
            float qem = chain2(zc.a[j] - zhm.a[j], zc.b[j] - zhm.b[j], sg1, nt0, nt1);
            o[j] = clip(zc.b[j], sg3) + pem[j] - pe[j] + qem - qe;
        }
        {
            float zax = __shfl_down_sync(FULLM, zc.a[0], 1);
            float zbx = __shfl_down_sync(FULLM, zc.b[0], 1);
            if (lane == 31) { zax = zc.a[3]; zbx = zc.b[3]; }
            float s[4];
            s[0] = chain2(zc.a[1] - zc.a[0], zc.b[1] - zc.b[0], sg2, nt0, nt1);
            s[1] = chain2(zc.a[2] - zc.a[1], zc.b[2] - zc.b[1], sg2, nt0, nt1);
            s[2] = chain2(zc.a[3] - zc.a[2], zc.b[3] - zc.b[2], sg2, nt0, nt1);
            s[3] = chain2(zax     - zc.a[3], zbx     - zc.b[3], sg2, nt0, nt1);
            float sem = __shfl_up_sync(FULLM, s[3], 1);
            o[0] += ((lane > 0) ? sem : 0.f) - s[0];
            o[1] += s[0] - s[1];
            o[2] += s[1] - s[2];
            o[3] += s[2] - s[3];
        }

        *(float4*)(tout + idx) = make_float4(o[0], o[1], o[2], o[3]);
        float4 s4 = ld4(sino, idx);
        float z2v[4] = { zf(o[0], s4.x), zf(o[1], s4.y), zf(o[2], s4.z), zf(o[3], s4.w) };
        sth4(wz2, idx, z2v);

#pragma unroll
        for (int j = 0; j < 4; j++) pem[j] = pe[j];
        zc = zn;
    }
}

// ---------------- cascade 2 ----------------
__global__ __launch_bounds__(256)
void dtv_c2(const unsigned int* __restrict__ zpk, const __half* __restrict__ z2,
            const float* __restrict__ sig, const float* __restrict__ ntp,
            float* __restrict__ tout)
{
    int h, d0;
    int idx0 = base_idx(h, d0);
    int lane = threadIdx.x & 31;
    bool hhi = (h < H_ - 1), hlo = (h > 0);

    float sg0 = __ldg(sig+0), sg1 = __ldg(sig+1), sg2 = __ldg(sig+2), sg3 = __ldg(sig+3);
    float nt0 = __ldg(ntp + 0), nt1 = __ldg(ntp + 1), nt2 = __ldg(ntp + 2);

    ZP zc = ldpk(zpk, idx0);
    float cc[4];
    ldh4(z2, idx0, cc);
    float pem[4] = {0.f, 0.f, 0.f, 0.f};
    if (d0 > 0) {
        ZP zm = ldpk(zpk, idx0 - SD_);
        float cm[4];
        ldh4(z2, idx0 - SD_, cm);
#pragma unroll
        for (int j = 0; j < 4; j++)
            pem[j] = chain3(zc.a[j]-zm.a[j], zc.b[j]-zm.b[j], cc[j]-cm[j], sg0, nt0, nt1, nt2);
    }

#pragma unroll 2
    for (int dd = 0; dd < CH; dd++) {
        int idx = idx0 + dd * SD_;
        int d = d0 + dd;

        ZP zn = zc;
        float cn[4] = { cc[0], cc[1], cc[2], cc[3] };
        if (d < D_ - 1) { zn = ldpk(zpk, idx + SD_); ldh4(z2, idx + SD_, cn); }

        ZP zhp = zc, zhm = zc;
        float chp[4] = { cc[0], cc[1], cc[2], cc[3] };
        float chm[4] = { cc[0], cc[1], cc[2], cc[3] };
        if (hhi) { zhp = ldpk(zpk, idx + W_); ldh4(z2, idx + W_, chp); }
        if (hlo) { zhm = ldpk(zpk, idx - W_); ldh4(z2, idx - W_, chm); }

        float o[4], pe[4];
#pragma unroll
        for (int j = 0; j < 4; j++) {
            pe[j] = chain3(zn.a[j]-zc.a[j],  zn.b[j]-zc.b[j],  cn[j]-cc[j],  sg0, nt0, nt1, nt2);
            float qe  = chain3(zhp.a[j]-zc.a[j], zhp.b[j]-zc.b[j], chp[j]-cc[j], sg1, nt0, nt1, nt2);
            float qem = chain3(zc.a[j]-zhm.a[j], zc.b[j]-zhm.b[j], cc[j]-chm[j], sg1, nt0, nt1, nt2);
            o[j] = clip(cc[j], sg3) + pem[j] - pe[j] + qem - qe;
        }
        {
            float zax = __shfl_down_sync(FULLM, zc.a[0], 1);
            float zbx = __shfl_down_sync(FULLM, zc.b[0], 1);
            float zcx = __shfl_down_sync(FULLM, cc[0],   1);
            if (lane == 31) { zax = zc.a[3]; zbx = zc.b[3]; zcx = cc[3]; }
            float s[4];
            s[0] = chain3(zc.a[1]-zc.a[0], zc.b[1]-zc.b[0], cc[1]-cc[0], sg2, nt0, nt1, nt2);
            s[1] = chain3(zc.a[2]-zc.a[1], zc.b[2]-zc.b[1], cc[2]-cc[1], sg2, nt0, nt1, nt2);
            s[2] = chain3(zc.a[3]-zc.a[2], zc.b[3]-zc.b[2], cc[3]-cc[2], sg2, nt0, nt1, nt2);
            s[3] = chain3(zax-zc.a[3],     zbx-zc.b[3],     zcx-cc[3],   sg2, nt0, nt1, nt2);
            float sem = __shfl_up_sync(FULLM, s[3], 1);
            o[0] += ((lane > 0) ? sem : 0.f) - s[0];
            o[1] += s[0] - s[1];
            o[2] += s[1] - s[2];
            o[3] += s[2] - s[3];
        }

        *(float4*)(tout + idx) = make_float4(o[0], o[1], o[2], o[3]);

#pragma unroll
        for (int j = 0; j < 4; j++) { pem[j] = pe[j]; cc[j] = cn[j]; }
        zc = zn;
    }
}

extern "C" void kernel_launch(void* const* d_in, const int* in_sizes, int n_in,
                              void* d_out, int out_size)
{
    const float* image = nullptr;
    const float* sino  = nullptr;
    const float* sigma = nullptr;
    const float* ntv   = nullptr;
    for (int i = 0; i < n_in; i++) {
        if (in_sizes[i] == 4) sigma = (const float*)d_in[i];
        else if (in_sizes[i] == 3) ntv = (const float*)d_in[i];
        else if (!image) image = (const float*)d_in[i];
        else if (!sino)  sino  = (const float*)d_in[i];
    }
    float* out = (float*)d_out;

    unsigned int* zpk;
    __half* z2a;
    cudaGetSymbolAddress((void**)&zpk, g_zpk);
    cudaGetSymbolAddress((void**)&z2a, g_z2);

    // threads = NVOX/4/CH = 524288 -> 2048 blocks of 256
    dim3 grid(NVOX / 4 / CH / 256), block(256);

    dtv_c0<<<grid, block>>>(image, sino, sigma, ntv, zpk, out + 1u * NVOX, out);
    dtv_c1<<<grid, block>>>(zpk, sino, sigma, ntv, z2a, out + 2u * NVOX);
    dtv_c2<<<grid, block>>>(zpk, z2a, sigma, ntv, out + 3u * NVOX);
}